// round 2
// baseline (speedup 1.0000x reference)
#include <cuda_runtime.h>

// XAJ hydrological scan: T=730 steps, B=16384 basins, evap MLP 8->16->8->1.
// Round 2: 2 basins per thread (ILP to fill latency stalls) + packed
// fma.rn.f32x2 to halve FMA-pipe issue cycles in the MLP.
#define T_STEPS 730
#define NBASIN  16384
#define HALF    8192
#define NH1     16
#define NH2     8
#define EPSV    1e-5f

// Packed 2xFP32 FMA (sm_100+; ptxas never auto-fuses — PTX only).
// Numerically identical to two independent fmaf's.
__device__ __forceinline__ float2 ffma2(float2 a, float2 b, float2 c) {
    float2 d;
    asm("fma.rn.f32x2 %0, %1, %2, %3;"
        : "=l"(reinterpret_cast<unsigned long long&>(d))
        : "l"(reinterpret_cast<unsigned long long&>(a)),
          "l"(reinterpret_cast<unsigned long long&>(b)),
          "l"(reinterpret_cast<unsigned long long&>(c)));
    return d;
}

__global__ __launch_bounds__(64, 1)
void xaj_dpl2_kernel(const float2* __restrict__ p_and_e,
                     const float*  __restrict__ kc_,
                     const float*  __restrict__ um_,
                     const float*  __restrict__ lm_,
                     const float*  __restrict__ dm_,
                     const float*  __restrict__ b_,
                     const float*  __restrict__ im_,
                     const float*  __restrict__ c_,
                     const float*  __restrict__ w0_,
                     const float*  __restrict__ W1,
                     const float*  __restrict__ b1,
                     const float*  __restrict__ W2,
                     const float*  __restrict__ b2,
                     const float*  __restrict__ W3,
                     const float*  __restrict__ b3,
                     float4*       __restrict__ out)
{
    // W2 [16,8] in shared; rows loaded per-step as LDS.128 broadcast.
    __shared__ float sW2[NH1 * NH2];
    for (int i = threadIdx.x; i < NH1 * NH2; i += 64) sW2[i] = W2[i];
    __syncthreads();

    const int tid0 = blockIdx.x * 64 + threadIdx.x;

    // ---- W1 live rows (w0c / prcp / pet), packed i-pairs; shared by both basins ----
    float2 w5p[8], w6p[8], w7p[8];
#pragma unroll
    for (int p = 0; p < 8; p++) {
        w5p[p] = make_float2(W1[5 * NH1 + 2 * p], W1[5 * NH1 + 2 * p + 1]);
        w6p[p] = make_float2(W1[6 * NH1 + 2 * p], W1[6 * NH1 + 2 * p + 1]);
        w7p[p] = make_float2(W1[7 * NH1 + 2 * p], W1[7 * NH1 + 2 * p + 1]);
    }
    float2 rb2p[4];
#pragma unroll
    for (int k = 0; k < 4; k++) rb2p[k] = make_float2(b2[2 * k], b2[2 * k + 1]);
    float rw3[NH2];
#pragma unroll
    for (int k = 0; k < NH2; k++) rw3[k] = W3[k];
    const float rb3 = b3[0];

    // ---- per-basin parameters and folded layer-1 constants ----
    int bas[2] = {tid0, tid0 + HALF};
    float kc[2], im[2], wm[2], one_b[2], wmm[2], inv_b1[2],
          inv_wm[2], inv_wmm[2], wm_eps[2], w[2];
    float2 h1bp[2][8];
#pragma unroll
    for (int u = 0; u < 2; u++) {
        const int bi = bas[u];
        kc[u] = kc_[bi];
        const float um = um_[bi], lm = lm_[bi], dm = dm_[bi];
        const float bb = b_[bi];
        im[u] = im_[bi];
        const float cc = c_[bi];
        w[u]  = w0_[bi];
        wm[u]      = um + lm + dm;
        one_b[u]   = 1.0f + bb;
        wmm[u]     = wm[u] * one_b[u];
        inv_b1[u]  = 1.0f / one_b[u];
        inv_wm[u]  = 1.0f / wm[u];
        inv_wmm[u] = 1.0f / wmm[u];
        wm_eps[u]  = wm[u] - EPSV;
#pragma unroll
        for (int p = 0; p < 8; p++) {
            float hb[2];
#pragma unroll
            for (int s = 0; s < 2; s++) {
                const int i = 2 * p + s;
                hb[s] = b1[i]
                      + kc[u] * W1[0 * NH1 + i]
                      + um    * W1[1 * NH1 + i]
                      + lm    * W1[2 * NH1 + i]
                      + dm    * W1[3 * NH1 + i]
                      + cc    * W1[4 * NH1 + i];
            }
            h1bp[u][p] = make_float2(hb[0], hb[1]);
        }
    }

    // ---- forcing prefetch (distance 2) for both basins ----
    const float2* peptr[2] = {p_and_e + bas[0], p_and_e + bas[1]};
    float2 pa[2], pb[2];
#pragma unroll
    for (int u = 0; u < 2; u++) { pa[u] = peptr[u][0]; pb[u] = peptr[u][NBASIN]; }

#pragma unroll 1
    for (int t = 0; t < T_STEPS; t++) {
        float prcp[2], pet[2], w0c[2];
#pragma unroll
        for (int u = 0; u < 2; u++) {
            const float2 pe = pa[u];
            pa[u] = pb[u];
            if (t + 2 < T_STEPS) pb[u] = peptr[u][(size_t)(t + 2) * NBASIN];
            prcp[u] = fmaxf(pe.x, 0.0f);
            pet[u]  = fmaxf(pe.y, 0.0f);
            w0c[u]  = fminf(fmaxf(w[u], 0.0f), wm_eps[u]);
        }

        // ---- layer 1: packed i-pairs, both basins interleaved ----
        float2 h[2][8];
#pragma unroll
        for (int u = 0; u < 2; u++) {
            const float2 dw0 = make_float2(w0c[u],  w0c[u]);
            const float2 dpr = make_float2(prcp[u], prcp[u]);
            const float2 dpe = make_float2(pet[u],  pet[u]);
#pragma unroll
            for (int p = 0; p < 8; p++) {
                float2 hh = ffma2(dw0, w5p[p], h1bp[u][p]);
                hh = ffma2(dpr, w6p[p], hh);
                hh = ffma2(dpe, w7p[p], hh);
                h[u][p] = make_float2(fmaxf(hh.x, 0.0f), fmaxf(hh.y, 0.0f));
            }
        }

        // ---- layer 2: 16x8 matvec, accumulators packed (k,k+1), 2 basins ----
        float2 a01[2], a23[2], a45[2], a67[2];
#pragma unroll
        for (int u = 0; u < 2; u++) {
            a01[u] = rb2p[0]; a23[u] = rb2p[1]; a45[u] = rb2p[2]; a67[u] = rb2p[3];
        }
#pragma unroll
        for (int j = 0; j < NH1; j++) {
            const float4 wA = *reinterpret_cast<const float4*>(&sW2[j * NH2]);
            const float4 wB = *reinterpret_cast<const float4*>(&sW2[j * NH2 + 4]);
            const float2 w01 = make_float2(wA.x, wA.y);
            const float2 w23 = make_float2(wA.z, wA.w);
            const float2 w45 = make_float2(wB.x, wB.y);
            const float2 w67 = make_float2(wB.z, wB.w);
#pragma unroll
            for (int u = 0; u < 2; u++) {
                const float hj = (j & 1) ? h[u][j >> 1].y : h[u][j >> 1].x;
                const float2 hh = make_float2(hj, hj);
                a01[u] = ffma2(hh, w01, a01[u]);
                a23[u] = ffma2(hh, w23, a23[u]);
                a45[u] = ffma2(hh, w45, a45[u]);
                a67[u] = ffma2(hh, w67, a67[u]);
            }
        }

        // ---- layer 3 + sigmoid + XAJ water balance, scalar per basin ----
#pragma unroll
        for (int u = 0; u < 2; u++) {
            float y0 = rb3 + fmaxf(a01[u].x, 0.0f) * rw3[0];
            float y1 = fmaxf(a01[u].y, 0.0f) * rw3[1];
            float y2 = fmaxf(a23[u].x, 0.0f) * rw3[2];
            float y3 = fmaxf(a23[u].y, 0.0f) * rw3[3];
            y0 += fmaxf(a45[u].x, 0.0f) * rw3[4];
            y1 += fmaxf(a45[u].y, 0.0f) * rw3[5];
            y2 += fmaxf(a67[u].x, 0.0f) * rw3[6];
            y3 += fmaxf(a67[u].y, 0.0f) * rw3[7];
            const float y = (y0 + y1) + (y2 + y3);

            const float sig = 1.0f / (1.0f + __expf(-y));
            const float e   = sig * kc[u] * pet[u];

            const float pd     = prcp[u] - e;
            const float pe_net = fmaxf(pd, 0.0f);
            const float frac   = fminf(fmaxf(1.0f - w0c[u] * inv_wm[u], EPSV), 1.0f);
            const float a      = wmm[u] * (1.0f - __powf(frac, inv_b1[u]));
            const float r_full = pe_net - (wm[u] - w0c[u]);
            const float resid  = fminf(fmaxf(1.0f - (pe_net + a) * inv_wmm[u], 0.0f), 1.0f);
            // resid clamps to 0 exactly when pe_net + a >= wmm, and powf(0, 1+b) = 0,
            // so this is branchlessly identical to the reference where().
            const float r   = fmaxf(r_full + wm[u] * __powf(resid, one_b[u]), 0.0f);
            const float rim = pe_net * im[u];

            w[u] = fminf(fmaxf(w0c[u] + pd - r, 0.0f), wm_eps[u]);

            out[(size_t)t * NBASIN + bas[u]] = make_float4(r, rim, e, pe_net);
        }
    }
}

extern "C" void kernel_launch(void* const* d_in, const int* in_sizes, int n_in,
                              void* d_out, int out_size)
{
    (void)in_sizes; (void)n_in; (void)out_size;
    const float2* p_and_e = (const float2*)d_in[0];
    const float*  kc = (const float*)d_in[1];
    const float*  um = (const float*)d_in[2];
    const float*  lm = (const float*)d_in[3];
    const float*  dm = (const float*)d_in[4];
    const float*  b  = (const float*)d_in[5];
    const float*  im = (const float*)d_in[6];
    const float*  c  = (const float*)d_in[7];
    const float*  w0 = (const float*)d_in[8];
    const float*  W1 = (const float*)d_in[9];
    const float*  b1 = (const float*)d_in[10];
    const float*  W2 = (const float*)d_in[11];
    const float*  b2 = (const float*)d_in[12];
    const float*  W3 = (const float*)d_in[13];
    const float*  b3 = (const float*)d_in[14];
    float4* out = (float4*)d_out;

    // 8192 threads, 2 basins each: 128 blocks x 64 threads -> 2 warps/block on
    // 128 SMs (2 SMSPs busy per SM, each with one high-ILP warp).
    xaj_dpl2_kernel<<<128, 64>>>(p_and_e, kc, um, lm, dm, b, im, c, w0,
                                 W1, b1, W2, b2, W3, b3, out);
}

// round 3
// speedup vs baseline: 1.2353x; 1.2353x over previous
#include <cuda_runtime.h>

// XAJ hydrological scan: T=730, B=16384, evap MLP 8->16->8->1.
// Round 3: back to 1 basin/thread (512 warps = max SMSP fill), with
// f32x2 packing within the basin + software-pipelined forcing-only layer-1
// partials to fill the serial XAJ/MUFU tail.
#define T_STEPS 730
#define NBASIN  16384
#define NH1     16
#define NH2     8
#define EPSV    1e-5f

// Packed 2xFP32 FMA (sm_100+; PTX-only, ptxas never auto-fuses).
__device__ __forceinline__ float2 ffma2(float2 a, float2 b, float2 c) {
    float2 d;
    asm("fma.rn.f32x2 %0, %1, %2, %3;"
        : "=l"(reinterpret_cast<unsigned long long&>(d))
        : "l"(reinterpret_cast<unsigned long long&>(a)),
          "l"(reinterpret_cast<unsigned long long&>(b)),
          "l"(reinterpret_cast<unsigned long long&>(c)));
    return d;
}
__device__ __forceinline__ float2 fadd2(float2 a, float2 b) {
    float2 d;
    asm("add.rn.f32x2 %0, %1, %2;"
        : "=l"(reinterpret_cast<unsigned long long&>(d))
        : "l"(reinterpret_cast<unsigned long long&>(a)),
          "l"(reinterpret_cast<unsigned long long&>(b)));
    return d;
}
// Duplicate a scalar into both lanes of an aligned pair (1 MOV).
__device__ __forceinline__ float2 dup2(float s) {
    float2 d;
    asm("mov.b64 %0, {%1, %1};"
        : "=l"(reinterpret_cast<unsigned long long&>(d)) : "f"(s));
    return d;
}

__global__ __launch_bounds__(128, 1)
void xaj_dpl3_kernel(const float2* __restrict__ p_and_e,
                     const float*  __restrict__ kc_,
                     const float*  __restrict__ um_,
                     const float*  __restrict__ lm_,
                     const float*  __restrict__ dm_,
                     const float*  __restrict__ b_,
                     const float*  __restrict__ im_,
                     const float*  __restrict__ c_,
                     const float*  __restrict__ w0_,
                     const float*  __restrict__ W1,
                     const float*  __restrict__ b1,
                     const float*  __restrict__ W2,
                     const float*  __restrict__ b2,
                     const float*  __restrict__ W3,
                     const float*  __restrict__ b3,
                     float4*       __restrict__ out)
{
    // W2 [16,8] broadcast from shared via LDS.128 (conflict-free broadcast).
    __shared__ float sW2[NH1 * NH2];
    if (threadIdx.x < NH1 * NH2) sW2[threadIdx.x] = W2[threadIdx.x];
    __syncthreads();

    const int bas = blockIdx.x * blockDim.x + threadIdx.x;

    // Per-basin constants
    const float kc = kc_[bas];
    const float um = um_[bas];
    const float lm = lm_[bas];
    const float dm = dm_[bas];
    const float bb = b_[bas];
    const float im = im_[bas];
    const float cc = c_[bas];
    float w = w0_[bas];

    const float wm      = um + lm + dm;
    const float one_b   = 1.0f + bb;
    const float wmm     = wm * one_b;
    const float inv_b1  = 1.0f / one_b;
    const float inv_wm  = 1.0f / wm;
    const float inv_wmm = 1.0f / wmm;
    const float wm_eps  = wm - EPSV;

    // Layer-1 weights as hidden-unit pairs; constant features folded into h1bp.
    float2 w5p[8], w6p[8], w7p[8], h1bp[8];
#pragma unroll
    for (int p = 0; p < 8; p++) {
        const int i0 = 2 * p, i1 = 2 * p + 1;
        w5p[p] = make_float2(W1[5 * NH1 + i0], W1[5 * NH1 + i1]);
        w6p[p] = make_float2(W1[6 * NH1 + i0], W1[6 * NH1 + i1]);
        w7p[p] = make_float2(W1[7 * NH1 + i0], W1[7 * NH1 + i1]);
        float hb0 = b1[i0] + kc * W1[i0] + um * W1[NH1 + i0] + lm * W1[2 * NH1 + i0]
                  + dm * W1[3 * NH1 + i0] + cc * W1[4 * NH1 + i0];
        float hb1 = b1[i1] + kc * W1[i1] + um * W1[NH1 + i1] + lm * W1[2 * NH1 + i1]
                  + dm * W1[3 * NH1 + i1] + cc * W1[4 * NH1 + i1];
        h1bp[p] = make_float2(hb0, hb1);
    }
    float2 rb2p[4];
#pragma unroll
    for (int k = 0; k < 4; k++) rb2p[k] = make_float2(b2[2 * k], b2[2 * k + 1]);
    float rw3[NH2];
#pragma unroll
    for (int k = 0; k < NH2; k++) rw3[k] = W3[k];
    const float rb3 = b3[0];

    // ---- forcing pipeline: cur scalars + next float2 + in-flight prefetch ----
    const float2* pe_ptr = p_and_e + bas;
    float2 pe_nxt = pe_ptr[NBASIN];
    {
        // t=0 forcing + its forcing-only layer-1 partial
    }
    float2 pe0 = pe_ptr[0];
    float prcp = fmaxf(pe0.x, 0.0f);
    float pet  = fmaxf(pe0.y, 0.0f);
    float kpet = kc * pet;

    float2 pre[8];
    {
        const float2 prd = dup2(prcp), ped = dup2(pet);
#pragma unroll
        for (int p = 0; p < 8; p++)
            pre[p] = ffma2(ped, w7p[p], ffma2(prd, w6p[p], h1bp[p]));
    }

    float4* out_ptr = out + bas;

#pragma unroll 2
    for (int t = 0; t < T_STEPS; t++) {
        // prefetch forcing for t+2 (distance 2 hides DRAM latency)
        float2 pe_f = pe_nxt;
        if (t + 2 < T_STEPS) pe_f = pe_ptr[(size_t)(t + 2) * NBASIN];

        const float w0c = fminf(fmaxf(w, 0.0f), wm_eps);

        // ---- layer 1: pre (forcing-only, computed last step) + w0c term ----
        float2 h[8];
        {
            const float2 w0d = dup2(w0c);
#pragma unroll
            for (int p = 0; p < 8; p++) {
                float2 hh = ffma2(w0d, w5p[p], pre[p]);
                h[p] = make_float2(fmaxf(hh.x, 0.0f), fmaxf(hh.y, 0.0f));
            }
        }

        // ---- start the w0c-only MUFU chain early so powf overlaps layer 2 ----
        const float frac = fminf(fmaxf(1.0f - w0c * inv_wm, EPSV), 1.0f);
        const float a_xaj = wmm * (1.0f - __powf(frac, inv_b1));
        const float r_base = w0c - wm;  // r_full = pe_net + r_base

        // ---- layer 2: 16x8 matvec, packed output pairs, even/odd-j chains ----
        float2 e01 = rb2p[0], e23 = rb2p[1], e45 = rb2p[2], e67 = rb2p[3];
        float2 o01 = make_float2(0.f, 0.f), o23 = o01, o45 = o01, o67 = o01;
#pragma unroll
        for (int p = 0; p < 8; p++) {
            const float4 wA0 = *reinterpret_cast<const float4*>(&sW2[(2 * p) * NH2]);
            const float4 wB0 = *reinterpret_cast<const float4*>(&sW2[(2 * p) * NH2 + 4]);
            const float4 wA1 = *reinterpret_cast<const float4*>(&sW2[(2 * p + 1) * NH2]);
            const float4 wB1 = *reinterpret_cast<const float4*>(&sW2[(2 * p + 1) * NH2 + 4]);
            const float2 hd0 = dup2(h[p].x);
            const float2 hd1 = dup2(h[p].y);
            e01 = ffma2(hd0, make_float2(wA0.x, wA0.y), e01);
            e23 = ffma2(hd0, make_float2(wA0.z, wA0.w), e23);
            e45 = ffma2(hd0, make_float2(wB0.x, wB0.y), e45);
            e67 = ffma2(hd0, make_float2(wB0.z, wB0.w), e67);
            o01 = ffma2(hd1, make_float2(wA1.x, wA1.y), o01);
            o23 = ffma2(hd1, make_float2(wA1.z, wA1.w), o23);
            o45 = ffma2(hd1, make_float2(wB1.x, wB1.y), o45);
            o67 = ffma2(hd1, make_float2(wB1.z, wB1.w), o67);
        }
        const float2 a01 = fadd2(e01, o01);
        const float2 a23 = fadd2(e23, o23);
        const float2 a45 = fadd2(e45, o45);
        const float2 a67 = fadd2(e67, o67);

        // ---- layer 3 (scalar tree) ----
        float y0 = rb3 + fmaxf(a01.x, 0.0f) * rw3[0];
        float y1 = fmaxf(a01.y, 0.0f) * rw3[1];
        float y2 = fmaxf(a23.x, 0.0f) * rw3[2];
        float y3 = fmaxf(a23.y, 0.0f) * rw3[3];
        y0 += fmaxf(a45.x, 0.0f) * rw3[4];
        y1 += fmaxf(a45.y, 0.0f) * rw3[5];
        y2 += fmaxf(a67.x, 0.0f) * rw3[6];
        y3 += fmaxf(a67.y, 0.0f) * rw3[7];
        const float y = (y0 + y1) + (y2 + y3);

        // ---- sigmoid (MUFU EX2 + MUFU RCP via fdividef) ----
        const float ex  = __expf(-y);
        const float e   = __fdividef(kpet, 1.0f + ex);   // sig * kc * pet

        // ---- next step's forcing-only layer-1 partial: fills the tail ----
        const float prcp_n = fmaxf(pe_nxt.x, 0.0f);
        const float pet_n  = fmaxf(pe_nxt.y, 0.0f);
        const float kpet_n = kc * pet_n;
        {
            const float2 prd = dup2(prcp_n), ped = dup2(pet_n);
#pragma unroll
            for (int p = 0; p < 8; p++)
                pre[p] = ffma2(ped, w7p[p], ffma2(prd, w6p[p], h1bp[p]));
        }

        // ---- XAJ water balance ----
        const float pd     = prcp - e;
        const float pe_net = fmaxf(pd, 0.0f);
        const float resid  = fminf(fmaxf(1.0f - (pe_net + a_xaj) * inv_wmm, 0.0f), 1.0f);
        // resid clamps to 0 exactly when pe_net + a >= wmm and powf(0, 1+b) = 0,
        // so this is branchlessly identical to the reference's where().
        const float r   = fmaxf(pe_net + r_base + wm * __powf(resid, one_b), 0.0f);
        const float rim = pe_net * im;

        w = fminf(fmaxf(w0c + pd - r, 0.0f), wm_eps);

        out_ptr[(size_t)t * NBASIN] = make_float4(r, rim, e, pe_net);

        // rotate forcing pipeline
        prcp = prcp_n; pet = pet_n; kpet = kpet_n;
        pe_nxt = pe_f;
    }
    (void)pet;
}

extern "C" void kernel_launch(void* const* d_in, const int* in_sizes, int n_in,
                              void* d_out, int out_size)
{
    (void)in_sizes; (void)n_in; (void)out_size;
    const float2* p_and_e = (const float2*)d_in[0];
    const float*  kc = (const float*)d_in[1];
    const float*  um = (const float*)d_in[2];
    const float*  lm = (const float*)d_in[3];
    const float*  dm = (const float*)d_in[4];
    const float*  b  = (const float*)d_in[5];
    const float*  im = (const float*)d_in[6];
    const float*  c  = (const float*)d_in[7];
    const float*  w0 = (const float*)d_in[8];
    const float*  W1 = (const float*)d_in[9];
    const float*  b1 = (const float*)d_in[10];
    const float*  W2 = (const float*)d_in[11];
    const float*  b2 = (const float*)d_in[12];
    const float*  W3 = (const float*)d_in[13];
    const float*  b3 = (const float*)d_in[14];
    float4* out = (float4*)d_out;

    // 16384 threads = 512 warps: max SMSP fill for this problem.
    // 128 blocks x 128 threads -> 4 warps/SM on 128 SMs, 1 warp per SMSP.
    xaj_dpl3_kernel<<<128, 128>>>(p_and_e, kc, um, lm, dm, b, im, c, w0,
                                  W1, b1, W2, b2, W3, b3, out);
}